// round 14
// baseline (speedup 1.0000x reference)
#include <cuda_runtime.h>
#include <cuda_bf16.h>
#include <cstdint>
#include <type_traits>

#define N_NODES 50000
#define N_EDGES 800000
#define RELS 8
#define BASES 30
#define DIM 128
#define NR (RELS * DIM)   // 1024
#define SCAN_B 512
#define SCAN_G ((N_NODES + SCAN_B - 1) / SCAN_B)   // 98

// ---------------- scratch (device globals; no allocation allowed) ----------------
__device__ float g_W[NR * DIM];                     // W2cat[(r*128+k)][o]
__device__ float g_aggx[(size_t)N_NODES * NR];      // [N,8,128] per-relation aggregates
__device__ float g_h[(size_t)N_NODES * DIM];        // layer-1 output
__device__ float g_agg2[(size_t)N_NODES * DIM];     // layer-2 aggregate
__device__ int   g_cnt2[N_NODES * RELS];
__device__ int   g_off2[N_NODES * RELS + 1];        // per-(node,rel) CSR offsets
__device__ int   g_cur2[N_NODES * RELS];
__device__ int   g_offn[N_NODES + 1];               // per-node CSR offsets
__device__ int   g_bsum[SCAN_G];
__device__ int   g_boff[SCAN_G + 1];
__device__ int   g_src[N_EDGES];                    // CSR-ordered src
__device__ float g_wt[N_EDGES];                     // CSR-ordered edge_norm

// ---------------- CSR build ----------------
__global__ void k_zero2() {
    int i = blockIdx.x * blockDim.x + threadIdx.x;
    if (i < N_NODES * RELS) g_cnt2[i] = 0;
}

__global__ void k_hist2(const int* __restrict__ ei, const int* __restrict__ et) {
    int e = blockIdx.x * blockDim.x + threadIdx.x;
    if (e < N_EDGES) {
        int dst = ei[N_EDGES + e];
        int rel = et[e];
        if ((unsigned)dst < N_NODES && (unsigned)rel < RELS)
            atomicAdd(&g_cnt2[dst * RELS + rel], 1);
    }
}

__global__ void k_scan_p1() {
    __shared__ int sw[16];
    int t = threadIdx.x;
    int i = blockIdx.x * SCAN_B + t;
    int lane = t & 31, wid = t >> 5;
    int v = 0;
    if (i < N_NODES) {
        int4 a = *(const int4*)&g_cnt2[i * RELS];
        int4 b = *(const int4*)&g_cnt2[i * RELS + 4];
        v = a.x + a.y + a.z + a.w + b.x + b.y + b.z + b.w;
    }
    int x = v;
    #pragma unroll
    for (int off = 1; off < 32; off <<= 1) {
        int s = __shfl_up_sync(0xffffffffu, x, off);
        if (lane >= off) x += s;
    }
    if (lane == 31) sw[wid] = x;
    __syncthreads();
    if (wid == 0 && lane < 16) {
        int w = sw[lane];
        #pragma unroll
        for (int off = 1; off < 16; off <<= 1) {
            int s = __shfl_up_sync(0xffffu, w, off);
            if (lane >= off) w += s;
        }
        sw[lane] = w;
    }
    __syncthreads();
    int warp_off = (wid > 0) ? sw[wid - 1] : 0;
    if (i < N_NODES) g_offn[i] = warp_off + x - v;
    if (t == SCAN_B - 1) g_bsum[blockIdx.x] = sw[15];
}

// phase 2: one warp, shuffle scan over 98 block sums (4 per lane)
__global__ void k_scan_p2() {
    int lane = threadIdx.x;             // 32 threads
    int v[4];
    #pragma unroll
    for (int j = 0; j < 4; j++) {
        int idx = lane * 4 + j;
        v[j] = (idx < SCAN_G) ? g_bsum[idx] : 0;
    }
    int s = v[0] + v[1] + v[2] + v[3];
    int x = s;
    #pragma unroll
    for (int off = 1; off < 32; off <<= 1) {
        int t = __shfl_up_sync(0xffffffffu, x, off);
        if (lane >= off) x += t;
    }
    int excl = x - s;
    #pragma unroll
    for (int j = 0; j < 4; j++) {
        int idx = lane * 4 + j;
        if (idx < SCAN_G) g_boff[idx] = excl;
        excl += v[j];
    }
    int total = __shfl_sync(0xffffffffu, x, 31);
    if (lane == 0) {
        g_boff[SCAN_G] = total;
        g_offn[N_NODES] = total;
        g_off2[N_NODES * RELS] = total;
    }
}

__global__ void k_scan_p3() {
    int i = blockIdx.x * SCAN_B + threadIdx.x;
    if (i >= N_NODES) return;
    int ex = g_offn[i] + g_boff[blockIdx.x];
    int4 a = *(const int4*)&g_cnt2[i * RELS];
    int4 b = *(const int4*)&g_cnt2[i * RELS + 4];
    int c[8] = { a.x, a.y, a.z, a.w, b.x, b.y, b.z, b.w };
    g_offn[i] = ex;
    int run = ex;
    #pragma unroll
    for (int r = 0; r < 8; r++) {
        g_off2[i * RELS + r] = run;
        g_cur2[i * RELS + r] = run;
        run += c[r];
    }
}

__global__ void k_scatter2(const int* __restrict__ ei, const int* __restrict__ et,
                           const float* __restrict__ norm) {
    int e = blockIdx.x * blockDim.x + threadIdx.x;
    if (e < N_EDGES) {
        int dst = ei[N_EDGES + e];
        int rel = et[e];
        if ((unsigned)dst < N_NODES && (unsigned)rel < RELS) {
            int src = ei[e];
            int p = atomicAdd(&g_cur2[dst * RELS + rel], 1);
            bool ok = (unsigned)src < N_NODES;
            g_src[p] = ok ? src : 0;
            g_wt[p]  = ok ? norm[e] : 0.f;
        }
    }
}

// ---------------- weights ----------------
__global__ void k_W(const float* __restrict__ basis, const float* __restrict__ comp) {
    int idx = blockIdx.x * blockDim.x + threadIdx.x;
    if (idx >= RELS * DIM * DIM) return;
    int o = idx & (DIM - 1);
    int k = (idx >> 7) & (DIM - 1);
    int r = idx >> 14;
    float s = 0.f;
    #pragma unroll
    for (int b = 0; b < BASES; b++)
        s += comp[r * BASES + b] * basis[((size_t)b * DIM + k) * DIM + o];
    g_W[idx] = s;
}

// ---------------- per-relation aggregation of raw x (warp per node), rel range ----
__global__ void k_aggX(const float* __restrict__ x, int r0, int r1)
{
    int n = blockIdx.x * (blockDim.x >> 5) + (threadIdx.x >> 5);
    if (n >= N_NODES) return;
    int lane = threadIdx.x & 31;
    #pragma unroll 1
    for (int r = r0; r < r1; r++) {
        int beg = g_off2[n * RELS + r], end = g_off2[n * RELS + r + 1];
        float4 acc = make_float4(0.f, 0.f, 0.f, 0.f);
        for (int p = beg; p < end; p++) {
            int s = g_src[p];
            float w = g_wt[p];
            float4 v = *((const float4*)(x + (size_t)s * DIM) + lane);
            acc.x += w * v.x; acc.y += w * v.y; acc.z += w * v.z; acc.w += w * v.w;
        }
        *((float4*)(g_aggx + (size_t)n * NR + r * DIM) + lane) = acc;
    }
}

// layer 2: g_agg2[n] = sum_{p in CSR[n]} g_h[src_p, :]
__global__ void k_agg2()
{
    int n = blockIdx.x * (blockDim.x >> 5) + (threadIdx.x >> 5);
    if (n >= N_NODES) return;
    int lane = threadIdx.x & 31;
    int beg = g_offn[n], end = g_offn[n + 1];
    float4 acc = make_float4(0.f, 0.f, 0.f, 0.f);
    for (int p = beg; p < end; p++) {
        int src = g_src[p];
        float4 v = *((const float4*)(g_h + (size_t)src * DIM) + lane);
        acc.x += v.x; acc.y += v.y; acc.z += v.z; acc.w += v.w;
    }
    *((float4*)(g_agg2 + (size_t)n * DIM) + lane) = acc;
}

// ---------------- tf32 tensor-core GEMM (R8-proven) ----------------
// AMODE: 3=concat[g_agg2|g_h] (KT=256), 5=concat[aggx(0:512)|x] (KT=640),
//        6=aggx(512:1024) (KT=512)
// BMODE: 2=concat[Bp|Bp2] (KT=256), 4=concat[g_W(0:512)|Bp2(root)] (KT=640),
//        5=g_W(512:1024) (KT=512)
// CMODE: 0=param, 2=g_h

__device__ __forceinline__ uint32_t f2tf(float f) {
    uint32_t u;
    asm volatile("cvt.rna.tf32.f32 %0, %1;" : "=r"(u) : "f"(f));
    return u;
}

__device__ __forceinline__ void mma_tf32(float* c, const uint32_t* a, const uint32_t* b) {
    asm volatile(
        "mma.sync.aligned.m16n8k8.row.col.f32.tf32.tf32.f32 "
        "{%0,%1,%2,%3}, {%4,%5,%6,%7}, {%8,%9}, {%0,%1,%2,%3};"
        : "+f"(c[0]), "+f"(c[1]), "+f"(c[2]), "+f"(c[3])
        : "r"(a[0]), "r"(a[1]), "r"(a[2]), "r"(a[3]), "r"(b[0]), "r"(b[1]));
}

template<int KT, int AMODE, int BMODE, int CMODE, bool ADD_C, bool HAS_BIAS>
__global__ __launch_bounds__(256, 2)
void k_gemm_tc(const float* __restrict__ Ap, const float* __restrict__ Bp,
               const float* __restrict__ Bp2, float* __restrict__ Cp,
               int M, int N, const float* __restrict__ bias)
{
    __shared__ __align__(16) uint32_t As[2][128][24];
    __shared__ __align__(16) uint32_t Bs[2][16][136];

    int tid  = threadIdx.x;
    int lane = tid & 31;
    int wid  = tid >> 5;
    int warp_m = wid & 1;
    int warp_n = wid >> 1;
    int m0 = blockIdx.y * 128;
    int n0 = blockIdx.x * 128;
    int r  = lane >> 2;
    int cq = lane & 3;

    float acc[4][4][4];
    #pragma unroll
    for (int mt = 0; mt < 4; mt++)
        #pragma unroll
        for (int nt = 0; nt < 4; nt++)
            #pragma unroll
            for (int i = 0; i < 4; i++) acc[mt][nt][i] = 0.f;

    float4 aReg[2], bReg[2];

    const int fa_m  = tid >> 2;
    const int fa_c4 = (tid & 3) * 4;
    const int fa_s0 = (fa_c4 & 8) | ((fa_c4 >> 2) & 1);

    auto LDG_chunk = [&](int k0) {       // k0 = element offset in K, multiple of 16
        const float* Asrc; int astride; int acol;
        if (AMODE == 3) {
            Asrc = (k0 < DIM) ? (const float*)g_agg2 : (const float*)g_h;
            acol = k0 & (DIM - 1); astride = DIM;
        } else if (AMODE == 5) {
            if (k0 < 512) { Asrc = (const float*)g_aggx; acol = k0; astride = NR; }
            else          { Asrc = Ap; acol = k0 - 512; astride = DIM; }
        } else if (AMODE == 6) {
            Asrc = (const float*)g_aggx; acol = 512 + k0; astride = NR;
        } else { Asrc = Ap; acol = k0; astride = KT; }
        #pragma unroll
        for (int l = 0; l < 2; l++) {
            int gm = m0 + fa_m + l * 64;
            aReg[l] = (gm < M) ? *(const float4*)&Asrc[(size_t)gm * astride + acol + fa_c4]
                               : make_float4(0.f, 0.f, 0.f, 0.f);
        }
        const float* Bsrc; int brow;
        if (BMODE == 2)      { Bsrc = (k0 < DIM) ? Bp : Bp2; brow = k0 & (DIM - 1); }
        else if (BMODE == 4) { if (k0 < 512) { Bsrc = (const float*)g_W; brow = k0; }
                               else          { Bsrc = Bp2; brow = k0 - 512; } }
        else if (BMODE == 5) { Bsrc = (const float*)g_W; brow = 512 + k0; }
        else { Bsrc = Bp; brow = k0; }
        #pragma unroll
        for (int l = 0; l < 2; l++) {
            int idx = tid + l * 256;
            int kr = idx >> 5;
            int c = (idx & 31) * 4;
            bReg[l] = *(const float4*)&Bsrc[(size_t)(brow + kr) * N + n0 + c];
        }
    };

    auto STS_chunk = [&](auto bufc) {
        constexpr int buf = decltype(bufc)::value;
        #pragma unroll
        for (int l = 0; l < 2; l++) {
            int m = fa_m + l * 64;
            As[buf][m][fa_s0 + 0] = f2tf(aReg[l].x);
            As[buf][m][fa_s0 + 2] = f2tf(aReg[l].y);
            As[buf][m][fa_s0 + 4] = f2tf(aReg[l].z);
            As[buf][m][fa_s0 + 6] = f2tf(aReg[l].w);
        }
        #pragma unroll
        for (int l = 0; l < 2; l++) {
            int idx = tid + l * 256;
            int kr = idx >> 5;
            int c = (idx & 31) * 4;
            *(uint4*)&Bs[buf][kr][c] =
                make_uint4(f2tf(bReg[l].x), f2tf(bReg[l].y), f2tf(bReg[l].z), f2tf(bReg[l].w));
        }
    };

    auto MMA_chunk = [&](auto bufc) {
        constexpr int buf = decltype(bufc)::value;
        #pragma unroll
        for (int kk = 0; kk < 16; kk += 8) {
            uint32_t afr[4][4], bfr[4][2];
            #pragma unroll
            for (int mt = 0; mt < 4; mt++) {
                int mb = warp_m * 64 + mt * 16;
                uint2 lo = *(const uint2*)&As[buf][mb + r][kk + 2 * cq];
                uint2 hi = *(const uint2*)&As[buf][mb + r + 8][kk + 2 * cq];
                afr[mt][0] = lo.x; afr[mt][1] = hi.x;
                afr[mt][2] = lo.y; afr[mt][3] = hi.y;
            }
            #pragma unroll
            for (int nt = 0; nt < 4; nt++) {
                int nb = warp_n * 32 + nt * 8;
                bfr[nt][0] = Bs[buf][kk + cq][nb + r];
                bfr[nt][1] = Bs[buf][kk + cq + 4][nb + r];
            }
            #pragma unroll
            for (int mt = 0; mt < 4; mt++)
                #pragma unroll
                for (int nt = 0; nt < 4; nt++)
                    mma_tf32(acc[mt][nt], afr[mt], bfr[nt]);
        }
    };

    std::integral_constant<int, 0> B0;
    std::integral_constant<int, 1> B1;

    const int NC = KT / 16;
    LDG_chunk(0);
    STS_chunk(B0);
    __syncthreads();
    #pragma unroll 1
    for (int c = 0; c < NC; c += 2) {
        LDG_chunk((c + 1) * 16);
        MMA_chunk(B0);
        STS_chunk(B1);
        __syncthreads();
        if (c + 2 < NC) LDG_chunk((c + 2) * 16);
        MMA_chunk(B1);
        if (c + 2 < NC) {
            STS_chunk(B0);
            __syncthreads();
        }
    }

    float* C = (CMODE == 0) ? Cp : g_h;
    #pragma unroll
    for (int mt = 0; mt < 4; mt++) {
        int mA = m0 + warp_m * 64 + mt * 16 + r;
        #pragma unroll
        for (int nt = 0; nt < 4; nt++) {
            int n = n0 + warp_n * 32 + nt * 8 + 2 * cq;
            if (mA < M) {
                float2 v = make_float2(acc[mt][nt][0], acc[mt][nt][1]);
                if (HAS_BIAS) { v.x += bias[n]; v.y += bias[n + 1]; }
                if (ADD_C) {
                    float2 o = *(const float2*)&C[(size_t)mA * N + n];
                    v.x += o.x; v.y += o.y;
                }
                *(float2*)&C[(size_t)mA * N + n] = v;
            }
            int mB = mA + 8;
            if (mB < M) {
                float2 v = make_float2(acc[mt][nt][2], acc[mt][nt][3]);
                if (HAS_BIAS) { v.x += bias[n]; v.y += bias[n + 1]; }
                if (ADD_C) {
                    float2 o = *(const float2*)&C[(size_t)mB * N + n];
                    v.x += o.x; v.y += o.y;
                }
                *(float2*)&C[(size_t)mB * N + n] = v;
            }
        }
    }
}

// ---------------- launch ----------------
extern "C" void kernel_launch(void* const* d_in, const int* in_sizes, int n_in,
                              void* d_out, int out_size)
{
    const float* x      = (const float*)d_in[0];
    const int*   ei     = (const int*)d_in[1];    // int64 in reference -> delivered as int32
    const int*   et     = (const int*)d_in[2];
    const float* norm   = (const float*)d_in[3];
    const float* basis  = (const float*)d_in[4];
    const float* comp   = (const float*)d_in[5];
    const float* root   = (const float*)d_in[6];
    const float* bias1  = (const float*)d_in[7];
    const float* w_rel  = (const float*)d_in[8];
    const float* b_rel  = (const float*)d_in[9];
    const float* w_root = (const float*)d_in[10];
    float* out = (float*)d_out;

    const int MBLK = (N_NODES + 127) / 128;   // 391

    static cudaStream_t s_side = nullptr;
    static cudaEvent_t ev_csr = nullptr, ev_a = nullptr, ev_b = nullptr;
    if (s_side == nullptr) {
        cudaStreamCreateWithFlags(&s_side, cudaStreamNonBlocking);
        cudaEventCreateWithFlags(&ev_csr, cudaEventDisableTiming);
        cudaEventCreateWithFlags(&ev_a, cudaEventDisableTiming);
        cudaEventCreateWithFlags(&ev_b, cudaEventDisableTiming);
    }

    // ---- CSR build on main stream (critical path) ----
    k_zero2<<<(N_NODES * RELS + 255) / 256, 256>>>();
    k_hist2<<<(N_EDGES + 255) / 256, 256>>>(ei, et);
    k_scan_p1<<<SCAN_G, SCAN_B>>>();
    k_scan_p2<<<1, 32>>>();
    k_scan_p3<<<SCAN_G, SCAN_B>>>();
    k_scatter2<<<(N_EDGES + 255) / 256, 256>>>(ei, et, norm);
    cudaEventRecord(ev_csr, 0);

    // ---- side stream: aggX halves (relations 0-3, then 4-7) ----
    cudaStreamWaitEvent(s_side, ev_csr, 0);
    k_aggX<<<(N_NODES + 7) / 8, 256, 0, s_side>>>(x, 0, 4);
    cudaEventRecord(ev_a, s_side);
    k_aggX<<<(N_NODES + 7) / 8, 256, 0, s_side>>>(x, 4, 8);
    cudaEventRecord(ev_b, s_side);

    // ---- main stream: weights (runs under aggX_a), then K-split GEMM1 ----
    k_W<<<(RELS * DIM * DIM + 255) / 256, 256>>>(basis, comp);
    cudaStreamWaitEvent(0, ev_a, 0);
    {   // h = [aggx(r0-3) | x] @ [W(0:512); root] + bias1   (K=640)
        dim3 grid(1, MBLK);
        k_gemm_tc<640, 5, 4, 2, false, true><<<grid, 256>>>(x, nullptr, root, nullptr,
                                                            N_NODES, DIM, bias1);
    }
    cudaStreamWaitEvent(0, ev_b, 0);
    {   // h += aggx(r4-7) @ W(512:1024)   (K=512, ADD_C)
        dim3 grid(1, MBLK);
        k_gemm_tc<512, 6, 5, 2, true, false><<<grid, 256>>>(nullptr, nullptr, nullptr, nullptr,
                                                            N_NODES, DIM, nullptr);
    }

    // ---- layer 2 ----
    k_agg2<<<(N_NODES + 7) / 8, 256>>>();
    {   // out = [agg2, h] @ [w_rel; w_root] + b_rel   (K=256)
        dim3 grid(1, MBLK);
        k_gemm_tc<256, 3, 2, 0, false, true><<<grid, 256>>>(nullptr, w_rel, w_root, out,
                                                            N_NODES, DIM, b_rel);
    }
}

// round 15
// speedup vs baseline: 1.1046x; 1.1046x over previous
#include <cuda_runtime.h>
#include <cuda_bf16.h>
#include <cstdint>
#include <type_traits>

#define N_NODES 50000
#define N_EDGES 800000
#define RELS 8
#define BASES 30
#define DIM 128
#define NR (RELS * DIM)   // 1024
#define SCAN_B 512
#define SCAN_G ((N_NODES + SCAN_B - 1) / SCAN_B)   // 98

// ---------------- scratch (device globals; no allocation allowed) ----------------
__device__ float g_W[NR * DIM];                     // W2cat[(r*128+k)][o]
__device__ float g_aggx[(size_t)N_NODES * NR];      // [N,8,128] per-relation aggregates
__device__ float g_h[(size_t)N_NODES * DIM];        // layer-1 output
__device__ float g_agg2[(size_t)N_NODES * DIM];     // layer-2 aggregate
__device__ int   g_cnt2[N_NODES * RELS];
__device__ int   g_off2[N_NODES * RELS + 1];        // per-(node,rel) CSR offsets
__device__ int   g_cur2[N_NODES * RELS];
__device__ int   g_offn[N_NODES + 1];               // per-node CSR offsets
__device__ int   g_bsum[SCAN_G];
__device__ int   g_boff[SCAN_G + 1];
__device__ int   g_src[N_EDGES];                    // CSR-ordered src
__device__ float g_wt[N_EDGES];                     // CSR-ordered edge_norm

// ---------------- CSR build ----------------
__global__ void k_zero2() {
    int i = blockIdx.x * blockDim.x + threadIdx.x;
    if (i < N_NODES * RELS) g_cnt2[i] = 0;
}

__global__ void k_hist2(const int* __restrict__ ei, const int* __restrict__ et) {
    int e = blockIdx.x * blockDim.x + threadIdx.x;
    if (e < N_EDGES) {
        int dst = ei[N_EDGES + e];
        int rel = et[e];
        if ((unsigned)dst < N_NODES && (unsigned)rel < RELS)
            atomicAdd(&g_cnt2[dst * RELS + rel], 1);
    }
}

__global__ void k_scan_p1() {
    __shared__ int sw[16];
    int t = threadIdx.x;
    int i = blockIdx.x * SCAN_B + t;
    int lane = t & 31, wid = t >> 5;
    int v = 0;
    if (i < N_NODES) {
        int4 a = *(const int4*)&g_cnt2[i * RELS];
        int4 b = *(const int4*)&g_cnt2[i * RELS + 4];
        v = a.x + a.y + a.z + a.w + b.x + b.y + b.z + b.w;
    }
    int x = v;
    #pragma unroll
    for (int off = 1; off < 32; off <<= 1) {
        int s = __shfl_up_sync(0xffffffffu, x, off);
        if (lane >= off) x += s;
    }
    if (lane == 31) sw[wid] = x;
    __syncthreads();
    if (wid == 0 && lane < 16) {
        int w = sw[lane];
        #pragma unroll
        for (int off = 1; off < 16; off <<= 1) {
            int s = __shfl_up_sync(0xffffu, w, off);
            if (lane >= off) w += s;
        }
        sw[lane] = w;
    }
    __syncthreads();
    int warp_off = (wid > 0) ? sw[wid - 1] : 0;
    if (i < N_NODES) g_offn[i] = warp_off + x - v;
    if (t == SCAN_B - 1) g_bsum[blockIdx.x] = sw[15];
}

// phase 2: one warp, shuffle scan over 98 block sums (4 per lane)
__global__ void k_scan_p2() {
    int lane = threadIdx.x;             // 32 threads
    int v[4];
    #pragma unroll
    for (int j = 0; j < 4; j++) {
        int idx = lane * 4 + j;
        v[j] = (idx < SCAN_G) ? g_bsum[idx] : 0;
    }
    int s = v[0] + v[1] + v[2] + v[3];
    int x = s;
    #pragma unroll
    for (int off = 1; off < 32; off <<= 1) {
        int t = __shfl_up_sync(0xffffffffu, x, off);
        if (lane >= off) x += t;
    }
    int excl = x - s;
    #pragma unroll
    for (int j = 0; j < 4; j++) {
        int idx = lane * 4 + j;
        if (idx < SCAN_G) g_boff[idx] = excl;
        excl += v[j];
    }
    int total = __shfl_sync(0xffffffffu, x, 31);
    if (lane == 0) {
        g_boff[SCAN_G] = total;
        g_offn[N_NODES] = total;
        g_off2[N_NODES * RELS] = total;
    }
}

__global__ void k_scan_p3() {
    int i = blockIdx.x * SCAN_B + threadIdx.x;
    if (i >= N_NODES) return;
    int ex = g_offn[i] + g_boff[blockIdx.x];
    int4 a = *(const int4*)&g_cnt2[i * RELS];
    int4 b = *(const int4*)&g_cnt2[i * RELS + 4];
    int c[8] = { a.x, a.y, a.z, a.w, b.x, b.y, b.z, b.w };
    g_offn[i] = ex;
    int run = ex;
    #pragma unroll
    for (int r = 0; r < 8; r++) {
        g_off2[i * RELS + r] = run;
        g_cur2[i * RELS + r] = run;
        run += c[r];
    }
}

__global__ void k_scatter2(const int* __restrict__ ei, const int* __restrict__ et,
                           const float* __restrict__ norm) {
    int e = blockIdx.x * blockDim.x + threadIdx.x;
    if (e < N_EDGES) {
        int dst = ei[N_EDGES + e];
        int rel = et[e];
        if ((unsigned)dst < N_NODES && (unsigned)rel < RELS) {
            int src = ei[e];
            int p = atomicAdd(&g_cur2[dst * RELS + rel], 1);
            bool ok = (unsigned)src < N_NODES;
            g_src[p] = ok ? src : 0;
            g_wt[p]  = ok ? norm[e] : 0.f;
        }
    }
}

// ---------------- weights ----------------
__global__ void k_W(const float* __restrict__ basis, const float* __restrict__ comp) {
    int idx = blockIdx.x * blockDim.x + threadIdx.x;
    if (idx >= RELS * DIM * DIM) return;
    int o = idx & (DIM - 1);
    int k = (idx >> 7) & (DIM - 1);
    int r = idx >> 14;
    float s = 0.f;
    #pragma unroll
    for (int b = 0; b < BASES; b++)
        s += comp[r * BASES + b] * basis[((size_t)b * DIM + k) * DIM + o];
    g_W[idx] = s;
}

// ---------------- per-relation aggregation of raw x (warp per node) ----------------
// aggx is write-once-read-once and 205MB: stream it past L2 (__stcs) so the hot
// 25.6MB x stays L2-resident for the 410MB of gathers.
__global__ void k_aggX(const float* __restrict__ x)
{
    int n = blockIdx.x * (blockDim.x >> 5) + (threadIdx.x >> 5);
    if (n >= N_NODES) return;
    int lane = threadIdx.x & 31;
    #pragma unroll 1
    for (int r = 0; r < RELS; r++) {
        int beg = g_off2[n * RELS + r], end = g_off2[n * RELS + r + 1];
        float4 acc = make_float4(0.f, 0.f, 0.f, 0.f);
        for (int p = beg; p < end; p++) {
            int s = g_src[p];
            float w = g_wt[p];
            float4 v = *((const float4*)(x + (size_t)s * DIM) + lane);
            acc.x += w * v.x; acc.y += w * v.y; acc.z += w * v.z; acc.w += w * v.w;
        }
        __stcs((float4*)(g_aggx + (size_t)n * NR + r * DIM) + lane, acc);
    }
}

// layer 2: g_agg2[n] = sum_{p in CSR[n]} g_h[src_p, :]
__global__ void k_agg2()
{
    int n = blockIdx.x * (blockDim.x >> 5) + (threadIdx.x >> 5);
    if (n >= N_NODES) return;
    int lane = threadIdx.x & 31;
    int beg = g_offn[n], end = g_offn[n + 1];
    float4 acc = make_float4(0.f, 0.f, 0.f, 0.f);
    for (int p = beg; p < end; p++) {
        int src = g_src[p];
        float4 v = *((const float4*)(g_h + (size_t)src * DIM) + lane);
        acc.x += v.x; acc.y += v.y; acc.z += v.z; acc.w += v.w;
    }
    *((float4*)(g_agg2 + (size_t)n * DIM) + lane) = acc;
}

// ---------------- tf32 tensor-core GEMM (R8-proven) ----------------
// AMODE: 3=concat[g_agg2|g_h] (KT=256), 4=concat[g_aggx|Ap(x)] (KT=1152)
// BMODE: 2=concat[Bp|Bp2] (KT=256), 3=concat[g_W|Bp2(root)] (KT=1152)
// CMODE: 0=param, 2=g_h
// AMODE 4's aggx region is read-once -> __ldcs (evict-first).

__device__ __forceinline__ uint32_t f2tf(float f) {
    uint32_t u;
    asm volatile("cvt.rna.tf32.f32 %0, %1;" : "=r"(u) : "f"(f));
    return u;
}

__device__ __forceinline__ void mma_tf32(float* c, const uint32_t* a, const uint32_t* b) {
    asm volatile(
        "mma.sync.aligned.m16n8k8.row.col.f32.tf32.tf32.f32 "
        "{%0,%1,%2,%3}, {%4,%5,%6,%7}, {%8,%9}, {%0,%1,%2,%3};"
        : "+f"(c[0]), "+f"(c[1]), "+f"(c[2]), "+f"(c[3])
        : "r"(a[0]), "r"(a[1]), "r"(a[2]), "r"(a[3]), "r"(b[0]), "r"(b[1]));
}

template<int KT, int AMODE, int BMODE, int CMODE, bool ADD_C, bool HAS_BIAS>
__global__ __launch_bounds__(256, 2)
void k_gemm_tc(const float* __restrict__ Ap, const float* __restrict__ Bp,
               const float* __restrict__ Bp2, float* __restrict__ Cp,
               int M, int N, const float* __restrict__ bias)
{
    __shared__ __align__(16) uint32_t As[2][128][24];
    __shared__ __align__(16) uint32_t Bs[2][16][136];

    int tid  = threadIdx.x;
    int lane = tid & 31;
    int wid  = tid >> 5;
    int warp_m = wid & 1;
    int warp_n = wid >> 1;
    int m0 = blockIdx.y * 128;
    int n0 = blockIdx.x * 128;
    int r  = lane >> 2;
    int cq = lane & 3;

    float acc[4][4][4];
    #pragma unroll
    for (int mt = 0; mt < 4; mt++)
        #pragma unroll
        for (int nt = 0; nt < 4; nt++)
            #pragma unroll
            for (int i = 0; i < 4; i++) acc[mt][nt][i] = 0.f;

    float4 aReg[2], bReg[2];

    const int fa_m  = tid >> 2;
    const int fa_c4 = (tid & 3) * 4;
    const int fa_s0 = (fa_c4 & 8) | ((fa_c4 >> 2) & 1);

    auto LDG_chunk = [&](int k0) {       // k0 = element offset in K, multiple of 16
        const float* Asrc; int astride; int acol;
        bool streamA = false;
        if (AMODE == 3) {
            Asrc = (k0 < DIM) ? (const float*)g_agg2 : (const float*)g_h;
            acol = k0 & (DIM - 1); astride = DIM;
        } else if (AMODE == 4) {
            if (k0 < NR) { Asrc = (const float*)g_aggx; acol = k0; astride = NR; streamA = true; }
            else         { Asrc = Ap; acol = k0 - NR; astride = DIM; }
        } else { Asrc = Ap; acol = k0; astride = KT; }
        #pragma unroll
        for (int l = 0; l < 2; l++) {
            int gm = m0 + fa_m + l * 64;
            if (gm < M) {
                const float4* ap = (const float4*)&Asrc[(size_t)gm * astride + acol + fa_c4];
                aReg[l] = streamA ? __ldcs(ap) : *ap;
            } else {
                aReg[l] = make_float4(0.f, 0.f, 0.f, 0.f);
            }
        }
        const float* Bsrc; int brow;
        if (BMODE == 2)      { Bsrc = (k0 < DIM) ? Bp : Bp2; brow = k0 & (DIM - 1); }
        else if (BMODE == 3) { if (k0 < NR) { Bsrc = (const float*)g_W; brow = k0; }
                               else         { Bsrc = Bp2; brow = k0 - NR; } }
        else { Bsrc = Bp; brow = k0; }
        #pragma unroll
        for (int l = 0; l < 2; l++) {
            int idx = tid + l * 256;
            int kr = idx >> 5;
            int c = (idx & 31) * 4;
            bReg[l] = *(const float4*)&Bsrc[(size_t)(brow + kr) * N + n0 + c];
        }
    };

    auto STS_chunk = [&](auto bufc) {
        constexpr int buf = decltype(bufc)::value;
        #pragma unroll
        for (int l = 0; l < 2; l++) {
            int m = fa_m + l * 64;
            As[buf][m][fa_s0 + 0] = f2tf(aReg[l].x);
            As[buf][m][fa_s0 + 2] = f2tf(aReg[l].y);
            As[buf][m][fa_s0 + 4] = f2tf(aReg[l].z);
            As[buf][m][fa_s0 + 6] = f2tf(aReg[l].w);
        }
        #pragma unroll
        for (int l = 0; l < 2; l++) {
            int idx = tid + l * 256;
            int kr = idx >> 5;
            int c = (idx & 31) * 4;
            *(uint4*)&Bs[buf][kr][c] =
                make_uint4(f2tf(bReg[l].x), f2tf(bReg[l].y), f2tf(bReg[l].z), f2tf(bReg[l].w));
        }
    };

    auto MMA_chunk = [&](auto bufc) {
        constexpr int buf = decltype(bufc)::value;
        #pragma unroll
        for (int kk = 0; kk < 16; kk += 8) {
            uint32_t afr[4][4], bfr[4][2];
            #pragma unroll
            for (int mt = 0; mt < 4; mt++) {
                int mb = warp_m * 64 + mt * 16;
                uint2 lo = *(const uint2*)&As[buf][mb + r][kk + 2 * cq];
                uint2 hi = *(const uint2*)&As[buf][mb + r + 8][kk + 2 * cq];
                afr[mt][0] = lo.x; afr[mt][1] = hi.x;
                afr[mt][2] = lo.y; afr[mt][3] = hi.y;
            }
            #pragma unroll
            for (int nt = 0; nt < 4; nt++) {
                int nb = warp_n * 32 + nt * 8;
                bfr[nt][0] = Bs[buf][kk + cq][nb + r];
                bfr[nt][1] = Bs[buf][kk + cq + 4][nb + r];
            }
            #pragma unroll
            for (int mt = 0; mt < 4; mt++)
                #pragma unroll
                for (int nt = 0; nt < 4; nt++)
                    mma_tf32(acc[mt][nt], afr[mt], bfr[nt]);
        }
    };

    std::integral_constant<int, 0> B0;
    std::integral_constant<int, 1> B1;

    const int NC = KT / 16;
    LDG_chunk(0);
    STS_chunk(B0);
    __syncthreads();
    #pragma unroll 1
    for (int c = 0; c < NC; c += 2) {
        LDG_chunk((c + 1) * 16);
        MMA_chunk(B0);
        STS_chunk(B1);
        __syncthreads();
        if (c + 2 < NC) LDG_chunk((c + 2) * 16);
        MMA_chunk(B1);
        if (c + 2 < NC) {
            STS_chunk(B0);
            __syncthreads();
        }
    }

    float* C = (CMODE == 0) ? Cp : g_h;
    #pragma unroll
    for (int mt = 0; mt < 4; mt++) {
        int mA = m0 + warp_m * 64 + mt * 16 + r;
        #pragma unroll
        for (int nt = 0; nt < 4; nt++) {
            int n = n0 + warp_n * 32 + nt * 8 + 2 * cq;
            if (mA < M) {
                float2 v = make_float2(acc[mt][nt][0], acc[mt][nt][1]);
                if (HAS_BIAS) { v.x += bias[n]; v.y += bias[n + 1]; }
                if (ADD_C) {
                    float2 o = *(const float2*)&C[(size_t)mA * N + n];
                    v.x += o.x; v.y += o.y;
                }
                *(float2*)&C[(size_t)mA * N + n] = v;
            }
            int mB = mA + 8;
            if (mB < M) {
                float2 v = make_float2(acc[mt][nt][2], acc[mt][nt][3]);
                if (HAS_BIAS) { v.x += bias[n]; v.y += bias[n + 1]; }
                if (ADD_C) {
                    float2 o = *(const float2*)&C[(size_t)mB * N + n];
                    v.x += o.x; v.y += o.y;
                }
                *(float2*)&C[(size_t)mB * N + n] = v;
            }
        }
    }
}

// ---------------- launch ----------------
extern "C" void kernel_launch(void* const* d_in, const int* in_sizes, int n_in,
                              void* d_out, int out_size)
{
    const float* x      = (const float*)d_in[0];
    const int*   ei     = (const int*)d_in[1];    // int64 in reference -> delivered as int32
    const int*   et     = (const int*)d_in[2];
    const float* norm   = (const float*)d_in[3];
    const float* basis  = (const float*)d_in[4];
    const float* comp   = (const float*)d_in[5];
    const float* root   = (const float*)d_in[6];
    const float* bias1  = (const float*)d_in[7];
    const float* w_rel  = (const float*)d_in[8];
    const float* b_rel  = (const float*)d_in[9];
    const float* w_root = (const float*)d_in[10];
    float* out = (float*)d_out;

    const int MBLK = (N_NODES + 127) / 128;   // 391

    static cudaStream_t s_side = nullptr;
    static cudaEvent_t ev_fork = nullptr, ev_join = nullptr;
    if (s_side == nullptr) {
        cudaStreamCreateWithFlags(&s_side, cudaStreamNonBlocking);
        cudaEventCreateWithFlags(&ev_fork, cudaEventDisableTiming);
        cudaEventCreateWithFlags(&ev_join, cudaEventDisableTiming);
    }

    // ---- fork: weights on side stream, CSR build on main (critical path) ----
    cudaEventRecord(ev_fork, 0);
    cudaStreamWaitEvent(s_side, ev_fork, 0);
    k_W<<<(RELS * DIM * DIM + 255) / 256, 256, 0, s_side>>>(basis, comp);
    cudaEventRecord(ev_join, s_side);

    k_zero2<<<(N_NODES * RELS + 255) / 256, 256>>>();
    k_hist2<<<(N_EDGES + 255) / 256, 256>>>(ei, et);
    k_scan_p1<<<SCAN_G, SCAN_B>>>();
    k_scan_p2<<<1, 32>>>();
    k_scan_p3<<<SCAN_G, SCAN_B>>>();
    k_scatter2<<<(N_EDGES + 255) / 256, 256>>>(ei, et, norm);

    // per-relation aggregation of raw x (x is L2-resident)
    k_aggX<<<(N_NODES + 7) / 8, 256>>>(x);

    cudaStreamWaitEvent(0, ev_join, 0);
    // layer 1 in ONE concat GEMM: h = [aggX | x] @ [W2cat; root] + bias1, K=1152
    {
        dim3 grid(1, MBLK);
        k_gemm_tc<1152, 4, 3, 2, false, true><<<grid, 256>>>(x, nullptr, root, nullptr,
                                                             N_NODES, DIM, bias1);
    }
    // layer-2 aggregation -> g_agg2 (g_h is L2-resident)
    k_agg2<<<(N_NODES + 7) / 8, 256>>>();
    // out = [agg2, h] @ [w_rel; w_root] + b_rel   (fused K=256)
    {
        dim3 grid(1, MBLK);
        k_gemm_tc<256, 3, 2, 0, false, true><<<grid, 256>>>(nullptr, w_rel, w_root, out,
                                                            N_NODES, DIM, b_rel);
    }
}

// round 16
// speedup vs baseline: 1.1121x; 1.0068x over previous
#include <cuda_runtime.h>
#include <cuda_bf16.h>
#include <cstdint>
#include <type_traits>

#define N_NODES 50000
#define N_EDGES 800000
#define RELS 8
#define BASES 30
#define DIM 128
#define NR (RELS * DIM)   // 1024
#define SCAN_B 512
#define SCAN_G ((N_NODES + SCAN_B - 1) / SCAN_B)   // 98

// ---------------- scratch (device globals; no allocation allowed) ----------------
__device__ float g_W[NR * DIM];                     // W2cat[(r*128+k)][o]
__device__ float g_aggx[(size_t)N_NODES * NR];      // [N,8,128] per-relation aggregates
__device__ float g_h[(size_t)N_NODES * DIM];        // layer-1 output
__device__ float g_agg2[(size_t)N_NODES * DIM];     // layer-2 aggregate
__device__ int   g_cnt2[N_NODES * RELS];
__device__ int   g_off2[N_NODES * RELS + 1];        // per-(node,rel) CSR offsets
__device__ int   g_cur2[N_NODES * RELS];
__device__ int   g_offn[N_NODES + 1];               // per-node CSR offsets
__device__ int   g_bsum[SCAN_G];
__device__ uint2 g_edge[N_EDGES];                   // CSR-ordered {src, wt_bits}

// ---------------- CSR build ----------------
__global__ void k_zero2() {
    int i = blockIdx.x * blockDim.x + threadIdx.x;
    if (i < N_NODES * RELS) g_cnt2[i] = 0;
}

__global__ void k_hist2(const int* __restrict__ ei, const int* __restrict__ et) {
    int e = blockIdx.x * blockDim.x + threadIdx.x;
    if (e < N_EDGES) {
        int dst = ei[N_EDGES + e];
        int rel = et[e];
        if ((unsigned)dst < N_NODES && (unsigned)rel < RELS)
            atomicAdd(&g_cnt2[dst * RELS + rel], 1);
    }
}

__global__ void k_scan_p1() {
    __shared__ int sw[16];
    int t = threadIdx.x;
    int i = blockIdx.x * SCAN_B + t;
    int lane = t & 31, wid = t >> 5;
    int v = 0;
    if (i < N_NODES) {
        int4 a = *(const int4*)&g_cnt2[i * RELS];
        int4 b = *(const int4*)&g_cnt2[i * RELS + 4];
        v = a.x + a.y + a.z + a.w + b.x + b.y + b.z + b.w;
    }
    int x = v;
    #pragma unroll
    for (int off = 1; off < 32; off <<= 1) {
        int s = __shfl_up_sync(0xffffffffu, x, off);
        if (lane >= off) x += s;
    }
    if (lane == 31) sw[wid] = x;
    __syncthreads();
    if (wid == 0 && lane < 16) {
        int w = sw[lane];
        #pragma unroll
        for (int off = 1; off < 16; off <<= 1) {
            int s = __shfl_up_sync(0xffffu, w, off);
            if (lane >= off) w += s;
        }
        sw[lane] = w;
    }
    __syncthreads();
    int warp_off = (wid > 0) ? sw[wid - 1] : 0;
    if (i < N_NODES) g_offn[i] = warp_off + x - v;
    if (t == SCAN_B - 1) g_bsum[blockIdx.x] = sw[15];
}

// p3 (merged with former p2): per-block offset recomputed from g_bsum via
// masked warp reduction, then expand per-relation sub-offsets.
__global__ void k_scan_p3() {
    __shared__ int s_boff, s_tot;
    if (threadIdx.x < 32) {
        int lane = threadIdx.x;
        int m = 0, t = 0;
        #pragma unroll
        for (int j = 0; j < 4; j++) {
            int idx = lane * 4 + j;
            int v = (idx < SCAN_G) ? g_bsum[idx] : 0;
            t += v;
            if (idx < blockIdx.x) m += v;
        }
        int boff = __reduce_add_sync(0xffffffffu, m);
        int tot  = __reduce_add_sync(0xffffffffu, t);
        if (lane == 0) { s_boff = boff; s_tot = tot; }
    }
    __syncthreads();
    if (blockIdx.x == 0 && threadIdx.x == 0) {
        g_offn[N_NODES] = s_tot;
        g_off2[N_NODES * RELS] = s_tot;
    }
    int i = blockIdx.x * SCAN_B + threadIdx.x;
    if (i >= N_NODES) return;
    int ex = g_offn[i] + s_boff;
    int4 a = *(const int4*)&g_cnt2[i * RELS];
    int4 b = *(const int4*)&g_cnt2[i * RELS + 4];
    int c[8] = { a.x, a.y, a.z, a.w, b.x, b.y, b.z, b.w };
    g_offn[i] = ex;
    int run = ex;
    #pragma unroll
    for (int r = 0; r < 8; r++) {
        g_off2[i * RELS + r] = run;
        g_cur2[i * RELS + r] = run;
        run += c[r];
    }
}

__global__ void k_scatter2(const int* __restrict__ ei, const int* __restrict__ et,
                           const float* __restrict__ norm) {
    int e = blockIdx.x * blockDim.x + threadIdx.x;
    if (e < N_EDGES) {
        int dst = ei[N_EDGES + e];
        int rel = et[e];
        if ((unsigned)dst < N_NODES && (unsigned)rel < RELS) {
            int src = ei[e];
            int p = atomicAdd(&g_cur2[dst * RELS + rel], 1);
            bool ok = (unsigned)src < N_NODES;
            g_edge[p] = make_uint2(ok ? (unsigned)src : 0u,
                                   ok ? __float_as_uint(norm[e]) : 0u);
        }
    }
}

// ---------------- weights ----------------
__global__ void k_W(const float* __restrict__ basis, const float* __restrict__ comp) {
    int idx = blockIdx.x * blockDim.x + threadIdx.x;
    if (idx >= RELS * DIM * DIM) return;
    int o = idx & (DIM - 1);
    int k = (idx >> 7) & (DIM - 1);
    int r = idx >> 14;
    float s = 0.f;
    #pragma unroll
    for (int b = 0; b < BASES; b++)
        s += comp[r * BASES + b] * basis[((size_t)b * DIM + k) * DIM + o];
    g_W[idx] = s;
}

// ---------------- per-relation aggregation of raw x (warp per node) ----------------
// aggx is write-once-read-once and 205MB: stream it past L2 (__stcs) so the hot
// 25.6MB x stays L2-resident for the 410MB of gathers.
__global__ void k_aggX(const float* __restrict__ x)
{
    int n = blockIdx.x * (blockDim.x >> 5) + (threadIdx.x >> 5);
    if (n >= N_NODES) return;
    int lane = threadIdx.x & 31;
    // coalesced load of the 9 segment offsets for this node
    int off = (lane < 9) ? g_off2[n * RELS + lane] : 0;
    #pragma unroll 1
    for (int r = 0; r < RELS; r++) {
        int beg = __shfl_sync(0xffffffffu, off, r);
        int end = __shfl_sync(0xffffffffu, off, r + 1);
        float4 acc = make_float4(0.f, 0.f, 0.f, 0.f);
        for (int p = beg; p < end; p++) {
            uint2 e = g_edge[p];               // broadcast 8B load
            int src = (int)e.x;
            float w = __uint_as_float(e.y);
            float4 v = *((const float4*)(x + (size_t)src * DIM) + lane);
            acc.x += w * v.x; acc.y += w * v.y; acc.z += w * v.z; acc.w += w * v.w;
        }
        __stcs((float4*)(g_aggx + (size_t)n * NR + r * DIM) + lane, acc);
    }
}

// layer 2: g_agg2[n] = sum_{p in CSR[n]} g_h[src_p, :]
__global__ void k_agg2()
{
    int n = blockIdx.x * (blockDim.x >> 5) + (threadIdx.x >> 5);
    if (n >= N_NODES) return;
    int lane = threadIdx.x & 31;
    int beg = g_offn[n], end = g_offn[n + 1];
    float4 acc = make_float4(0.f, 0.f, 0.f, 0.f);
    for (int p = beg; p < end; p++) {
        int src = (int)g_edge[p].x;
        float4 v = *((const float4*)(g_h + (size_t)src * DIM) + lane);
        acc.x += v.x; acc.y += v.y; acc.z += v.z; acc.w += v.w;
    }
    *((float4*)(g_agg2 + (size_t)n * DIM) + lane) = acc;
}

// ---------------- tf32 tensor-core GEMM (R8-proven, R15 cache hints) ----------------
// AMODE: 3=concat[g_agg2|g_h] (KT=256), 4=concat[g_aggx|Ap(x)] (KT=1152)
// BMODE: 2=concat[Bp|Bp2] (KT=256), 3=concat[g_W|Bp2(root)] (KT=1152)
// CMODE: 0=param, 2=g_h
// AMODE 4's aggx region is read-once -> __ldcs (evict-first).

__device__ __forceinline__ uint32_t f2tf(float f) {
    uint32_t u;
    asm volatile("cvt.rna.tf32.f32 %0, %1;" : "=r"(u) : "f"(f));
    return u;
}

__device__ __forceinline__ void mma_tf32(float* c, const uint32_t* a, const uint32_t* b) {
    asm volatile(
        "mma.sync.aligned.m16n8k8.row.col.f32.tf32.tf32.f32 "
        "{%0,%1,%2,%3}, {%4,%5,%6,%7}, {%8,%9}, {%0,%1,%2,%3};"
        : "+f"(c[0]), "+f"(c[1]), "+f"(c[2]), "+f"(c[3])
        : "r"(a[0]), "r"(a[1]), "r"(a[2]), "r"(a[3]), "r"(b[0]), "r"(b[1]));
}

template<int KT, int AMODE, int BMODE, int CMODE, bool ADD_C, bool HAS_BIAS>
__global__ __launch_bounds__(256, 2)
void k_gemm_tc(const float* __restrict__ Ap, const float* __restrict__ Bp,
               const float* __restrict__ Bp2, float* __restrict__ Cp,
               int M, int N, const float* __restrict__ bias)
{
    __shared__ __align__(16) uint32_t As[2][128][24];
    __shared__ __align__(16) uint32_t Bs[2][16][136];

    int tid  = threadIdx.x;
    int lane = tid & 31;
    int wid  = tid >> 5;
    int warp_m = wid & 1;
    int warp_n = wid >> 1;
    int m0 = blockIdx.y * 128;
    int n0 = blockIdx.x * 128;
    int r  = lane >> 2;
    int cq = lane & 3;

    float acc[4][4][4];
    #pragma unroll
    for (int mt = 0; mt < 4; mt++)
        #pragma unroll
        for (int nt = 0; nt < 4; nt++)
            #pragma unroll
            for (int i = 0; i < 4; i++) acc[mt][nt][i] = 0.f;

    float4 aReg[2], bReg[2];

    const int fa_m  = tid >> 2;
    const int fa_c4 = (tid & 3) * 4;
    const int fa_s0 = (fa_c4 & 8) | ((fa_c4 >> 2) & 1);

    auto LDG_chunk = [&](int k0) {       // k0 = element offset in K, multiple of 16
        const float* Asrc; int astride; int acol;
        bool streamA = false;
        if (AMODE == 3) {
            Asrc = (k0 < DIM) ? (const float*)g_agg2 : (const float*)g_h;
            acol = k0 & (DIM - 1); astride = DIM;
        } else if (AMODE == 4) {
            if (k0 < NR) { Asrc = (const float*)g_aggx; acol = k0; astride = NR; streamA = true; }
            else         { Asrc = Ap; acol = k0 - NR; astride = DIM; }
        } else { Asrc = Ap; acol = k0; astride = KT; }
        #pragma unroll
        for (int l = 0; l < 2; l++) {
            int gm = m0 + fa_m + l * 64;
            if (gm < M) {
                const float4* ap = (const float4*)&Asrc[(size_t)gm * astride + acol + fa_c4];
                aReg[l] = streamA ? __ldcs(ap) : *ap;
            } else {
                aReg[l] = make_float4(0.f, 0.f, 0.f, 0.f);
            }
        }
        const float* Bsrc; int brow;
        if (BMODE == 2)      { Bsrc = (k0 < DIM) ? Bp : Bp2; brow = k0 & (DIM - 1); }
        else if (BMODE == 3) { if (k0 < NR) { Bsrc = (const float*)g_W; brow = k0; }
                               else         { Bsrc = Bp2; brow = k0 - NR; } }
        else { Bsrc = Bp; brow = k0; }
        #pragma unroll
        for (int l = 0; l < 2; l++) {
            int idx = tid + l * 256;
            int kr = idx >> 5;
            int c = (idx & 31) * 4;
            bReg[l] = *(const float4*)&Bsrc[(size_t)(brow + kr) * N + n0 + c];
        }
    };

    auto STS_chunk = [&](auto bufc) {
        constexpr int buf = decltype(bufc)::value;
        #pragma unroll
        for (int l = 0; l < 2; l++) {
            int m = fa_m + l * 64;
            As[buf][m][fa_s0 + 0] = f2tf(aReg[l].x);
            As[buf][m][fa_s0 + 2] = f2tf(aReg[l].y);
            As[buf][m][fa_s0 + 4] = f2tf(aReg[l].z);
            As[buf][m][fa_s0 + 6] = f2tf(aReg[l].w);
        }
        #pragma unroll
        for (int l = 0; l < 2; l++) {
            int idx = tid + l * 256;
            int kr = idx >> 5;
            int c = (idx & 31) * 4;
            *(uint4*)&Bs[buf][kr][c] =
                make_uint4(f2tf(bReg[l].x), f2tf(bReg[l].y), f2tf(bReg[l].z), f2tf(bReg[l].w));
        }
    };

    auto MMA_chunk = [&](auto bufc) {
        constexpr int buf = decltype(bufc)::value;
        #pragma unroll
        for (int kk = 0; kk < 16; kk += 8) {
            uint32_t afr[4][4], bfr[4][2];
            #pragma unroll
            for (int mt = 0; mt < 4; mt++) {
                int mb = warp_m * 64 + mt * 16;
                uint2 lo = *(const uint2*)&As[buf][mb + r][kk + 2 * cq];
                uint2 hi = *(const uint2*)&As[buf][mb + r + 8][kk + 2 * cq];
                afr[mt][0] = lo.x; afr[mt][1] = hi.x;
                afr[mt][2] = lo.y; afr[mt][3] = hi.y;
            }
            #pragma unroll
            for (int nt = 0; nt < 4; nt++) {
                int nb = warp_n * 32 + nt * 8;
                bfr[nt][0] = Bs[buf][kk + cq][nb + r];
                bfr[nt][1] = Bs[buf][kk + cq + 4][nb + r];
            }
            #pragma unroll
            for (int mt = 0; mt < 4; mt++)
                #pragma unroll
                for (int nt = 0; nt < 4; nt++)
                    mma_tf32(acc[mt][nt], afr[mt], bfr[nt]);
        }
    };

    std::integral_constant<int, 0> B0;
    std::integral_constant<int, 1> B1;

    const int NC = KT / 16;
    LDG_chunk(0);
    STS_chunk(B0);
    __syncthreads();
    #pragma unroll 1
    for (int c = 0; c < NC; c += 2) {
        LDG_chunk((c + 1) * 16);
        MMA_chunk(B0);
        STS_chunk(B1);
        __syncthreads();
        if (c + 2 < NC) LDG_chunk((c + 2) * 16);
        MMA_chunk(B1);
        if (c + 2 < NC) {
            STS_chunk(B0);
            __syncthreads();
        }
    }

    float* C = (CMODE == 0) ? Cp : g_h;
    #pragma unroll
    for (int mt = 0; mt < 4; mt++) {
        int mA = m0 + warp_m * 64 + mt * 16 + r;
        #pragma unroll
        for (int nt = 0; nt < 4; nt++) {
            int n = n0 + warp_n * 32 + nt * 8 + 2 * cq;
            if (mA < M) {
                float2 v = make_float2(acc[mt][nt][0], acc[mt][nt][1]);
                if (HAS_BIAS) { v.x += bias[n]; v.y += bias[n + 1]; }
                if (ADD_C) {
                    float2 o = *(const float2*)&C[(size_t)mA * N + n];
                    v.x += o.x; v.y += o.y;
                }
                *(float2*)&C[(size_t)mA * N + n] = v;
            }
            int mB = mA + 8;
            if (mB < M) {
                float2 v = make_float2(acc[mt][nt][2], acc[mt][nt][3]);
                if (HAS_BIAS) { v.x += bias[n]; v.y += bias[n + 1]; }
                if (ADD_C) {
                    float2 o = *(const float2*)&C[(size_t)mB * N + n];
                    v.x += o.x; v.y += o.y;
                }
                *(float2*)&C[(size_t)mB * N + n] = v;
            }
        }
    }
}

// ---------------- launch ----------------
extern "C" void kernel_launch(void* const* d_in, const int* in_sizes, int n_in,
                              void* d_out, int out_size)
{
    const float* x      = (const float*)d_in[0];
    const int*   ei     = (const int*)d_in[1];    // int64 in reference -> delivered as int32
    const int*   et     = (const int*)d_in[2];
    const float* norm   = (const float*)d_in[3];
    const float* basis  = (const float*)d_in[4];
    const float* comp   = (const float*)d_in[5];
    const float* root   = (const float*)d_in[6];
    const float* bias1  = (const float*)d_in[7];
    const float* w_rel  = (const float*)d_in[8];
    const float* b_rel  = (const float*)d_in[9];
    const float* w_root = (const float*)d_in[10];
    float* out = (float*)d_out;

    const int MBLK = (N_NODES + 127) / 128;   // 391

    static cudaStream_t s_side = nullptr;
    static cudaEvent_t ev_fork = nullptr, ev_join = nullptr;
    if (s_side == nullptr) {
        cudaStreamCreateWithFlags(&s_side, cudaStreamNonBlocking);
        cudaEventCreateWithFlags(&ev_fork, cudaEventDisableTiming);
        cudaEventCreateWithFlags(&ev_join, cudaEventDisableTiming);
    }

    // ---- fork: weights on side stream, CSR build on main (critical path) ----
    cudaEventRecord(ev_fork, 0);
    cudaStreamWaitEvent(s_side, ev_fork, 0);
    k_W<<<(RELS * DIM * DIM + 255) / 256, 256, 0, s_side>>>(basis, comp);
    cudaEventRecord(ev_join, s_side);

    k_zero2<<<(N_NODES * RELS + 255) / 256, 256>>>();
    k_hist2<<<(N_EDGES + 255) / 256, 256>>>(ei, et);
    k_scan_p1<<<SCAN_G, SCAN_B>>>();
    k_scan_p3<<<SCAN_G, SCAN_B>>>();
    k_scatter2<<<(N_EDGES + 255) / 256, 256>>>(ei, et, norm);

    // per-relation aggregation of raw x (x is L2-resident)
    k_aggX<<<(N_NODES + 7) / 8, 256>>>(x);

    cudaStreamWaitEvent(0, ev_join, 0);
    // layer 1 in ONE concat GEMM: h = [aggX | x] @ [W2cat; root] + bias1, K=1152
    {
        dim3 grid(1, MBLK);
        k_gemm_tc<1152, 4, 3, 2, false, true><<<grid, 256>>>(x, nullptr, root, nullptr,
                                                             N_NODES, DIM, bias1);
    }
    // layer-2 aggregation -> g_agg2 (g_h is L2-resident)
    k_agg2<<<(N_NODES + 7) / 8, 256>>>();
    // out = [agg2, h] @ [w_rel; w_root] + b_rel   (fused K=256)
    {
        dim3 grid(1, MBLK);
        k_gemm_tc<256, 3, 2, 0, false, true><<<grid, 256>>>(nullptr, w_rel, w_root, out,
                                                            N_NODES, DIM, b_rel);
    }
}

// round 17
// speedup vs baseline: 1.1124x; 1.0002x over previous
#include <cuda_runtime.h>
#include <cuda_bf16.h>
#include <cstdint>
#include <type_traits>

#define N_NODES 50000
#define N_EDGES 800000
#define RELS 8
#define BASES 30
#define DIM 128
#define NR (RELS * DIM)   // 1024
#define SCAN_B 512
#define SCAN_G ((N_NODES + SCAN_B - 1) / SCAN_B)   // 98

// ---------------- scratch (device globals; no allocation allowed) ----------------
__device__ float g_W[NR * DIM];                     // W2cat[(r*128+k)][o]
__device__ float g_aggx[(size_t)N_NODES * NR];      // [N,8,128] per-relation aggregates
__device__ float g_h[(size_t)N_NODES * DIM];        // layer-1 output
__device__ float g_agg2[(size_t)N_NODES * DIM];     // layer-2 aggregate
__device__ int   g_cnt2[N_NODES * RELS];
__device__ int   g_off2[N_NODES * RELS + 1];        // per-(node,rel) CSR offsets
__device__ int   g_cur2[N_NODES * RELS];
__device__ int   g_offn[N_NODES + 1];               // per-node CSR offsets
__device__ int   g_bsum[SCAN_G];
__device__ uint2 g_edge[N_EDGES];                   // CSR-ordered {src, wt_bits}

// ---------------- CSR build ----------------
__global__ void k_zero2() {
    int i = blockIdx.x * blockDim.x + threadIdx.x;
    if (i < N_NODES * RELS) g_cnt2[i] = 0;
}

__global__ void k_hist2(const int* __restrict__ ei, const int* __restrict__ et) {
    int e = blockIdx.x * blockDim.x + threadIdx.x;
    if (e < N_EDGES) {
        int dst = ei[N_EDGES + e];
        int rel = et[e];
        if ((unsigned)dst < N_NODES && (unsigned)rel < RELS)
            atomicAdd(&g_cnt2[dst * RELS + rel], 1);
    }
}

__global__ void k_scan_p1() {
    __shared__ int sw[16];
    int t = threadIdx.x;
    int i = blockIdx.x * SCAN_B + t;
    int lane = t & 31, wid = t >> 5;
    int v = 0;
    if (i < N_NODES) {
        int4 a = *(const int4*)&g_cnt2[i * RELS];
        int4 b = *(const int4*)&g_cnt2[i * RELS + 4];
        v = a.x + a.y + a.z + a.w + b.x + b.y + b.z + b.w;
    }
    int x = v;
    #pragma unroll
    for (int off = 1; off < 32; off <<= 1) {
        int s = __shfl_up_sync(0xffffffffu, x, off);
        if (lane >= off) x += s;
    }
    if (lane == 31) sw[wid] = x;
    __syncthreads();
    if (wid == 0 && lane < 16) {
        int w = sw[lane];
        #pragma unroll
        for (int off = 1; off < 16; off <<= 1) {
            int s = __shfl_up_sync(0xffffu, w, off);
            if (lane >= off) w += s;
        }
        sw[lane] = w;
    }
    __syncthreads();
    int warp_off = (wid > 0) ? sw[wid - 1] : 0;
    if (i < N_NODES) g_offn[i] = warp_off + x - v;
    if (t == SCAN_B - 1) g_bsum[blockIdx.x] = sw[15];
}

// p3: per-block offset recomputed from g_bsum via masked warp reduction,
// then expand per-relation sub-offsets.
__global__ void k_scan_p3() {
    __shared__ int s_boff, s_tot;
    if (threadIdx.x < 32) {
        int lane = threadIdx.x;
        int m = 0, t = 0;
        #pragma unroll
        for (int j = 0; j < 4; j++) {
            int idx = lane * 4 + j;
            int v = (idx < SCAN_G) ? g_bsum[idx] : 0;
            t += v;
            if (idx < blockIdx.x) m += v;
        }
        int boff = __reduce_add_sync(0xffffffffu, m);
        int tot  = __reduce_add_sync(0xffffffffu, t);
        if (lane == 0) { s_boff = boff; s_tot = tot; }
    }
    __syncthreads();
    if (blockIdx.x == 0 && threadIdx.x == 0) {
        g_offn[N_NODES] = s_tot;
        g_off2[N_NODES * RELS] = s_tot;
    }
    int i = blockIdx.x * SCAN_B + threadIdx.x;
    if (i >= N_NODES) return;
    int ex = g_offn[i] + s_boff;
    int4 a = *(const int4*)&g_cnt2[i * RELS];
    int4 b = *(const int4*)&g_cnt2[i * RELS + 4];
    int c[8] = { a.x, a.y, a.z, a.w, b.x, b.y, b.z, b.w };
    g_offn[i] = ex;
    int run = ex;
    #pragma unroll
    for (int r = 0; r < 8; r++) {
        g_off2[i * RELS + r] = run;
        g_cur2[i * RELS + r] = run;
        run += c[r];
    }
}

__global__ void k_scatter2(const int* __restrict__ ei, const int* __restrict__ et,
                           const float* __restrict__ norm) {
    int e = blockIdx.x * blockDim.x + threadIdx.x;
    if (e < N_EDGES) {
        int dst = ei[N_EDGES + e];
        int rel = et[e];
        if ((unsigned)dst < N_NODES && (unsigned)rel < RELS) {
            int src = ei[e];
            int p = atomicAdd(&g_cur2[dst * RELS + rel], 1);
            bool ok = (unsigned)src < N_NODES;
            g_edge[p] = make_uint2(ok ? (unsigned)src : 0u,
                                   ok ? __float_as_uint(norm[e]) : 0u);
        }
    }
}

// ---------------- weights ----------------
__global__ void k_W(const float* __restrict__ basis, const float* __restrict__ comp) {
    int idx = blockIdx.x * blockDim.x + threadIdx.x;
    if (idx >= RELS * DIM * DIM) return;
    int o = idx & (DIM - 1);
    int k = (idx >> 7) & (DIM - 1);
    int r = idx >> 14;
    float s = 0.f;
    #pragma unroll
    for (int b = 0; b < BASES; b++)
        s += comp[r * BASES + b] * basis[((size_t)b * DIM + k) * DIM + o];
    g_W[idx] = s;
}

// ---------------- per-relation aggregation of raw x (warp per node) ----------------
// 4-way software-pipelined gather loop: 4 independent row loads in flight,
// FMAs applied in original edge order (bitwise-identical accumulation).
__global__ void k_aggX(const float* __restrict__ x)
{
    int n = blockIdx.x * (blockDim.x >> 5) + (threadIdx.x >> 5);
    if (n >= N_NODES) return;
    int lane = threadIdx.x & 31;
    int off = (lane < 9) ? g_off2[n * RELS + lane] : 0;
    #pragma unroll 1
    for (int r = 0; r < RELS; r++) {
        int beg = __shfl_sync(0xffffffffu, off, r);
        int end = __shfl_sync(0xffffffffu, off, r + 1);
        float4 acc = make_float4(0.f, 0.f, 0.f, 0.f);
        int p = beg;
        for (; p + 4 <= end; p += 4) {
            uint2 e0 = g_edge[p];
            uint2 e1 = g_edge[p + 1];
            uint2 e2 = g_edge[p + 2];
            uint2 e3 = g_edge[p + 3];
            float4 v0 = *((const float4*)(x + (size_t)e0.x * DIM) + lane);
            float4 v1 = *((const float4*)(x + (size_t)e1.x * DIM) + lane);
            float4 v2 = *((const float4*)(x + (size_t)e2.x * DIM) + lane);
            float4 v3 = *((const float4*)(x + (size_t)e3.x * DIM) + lane);
            float w0 = __uint_as_float(e0.y), w1 = __uint_as_float(e1.y);
            float w2 = __uint_as_float(e2.y), w3 = __uint_as_float(e3.y);
            acc.x += w0 * v0.x; acc.y += w0 * v0.y; acc.z += w0 * v0.z; acc.w += w0 * v0.w;
            acc.x += w1 * v1.x; acc.y += w1 * v1.y; acc.z += w1 * v1.z; acc.w += w1 * v1.w;
            acc.x += w2 * v2.x; acc.y += w2 * v2.y; acc.z += w2 * v2.z; acc.w += w2 * v2.w;
            acc.x += w3 * v3.x; acc.y += w3 * v3.y; acc.z += w3 * v3.z; acc.w += w3 * v3.w;
        }
        for (; p < end; p++) {
            uint2 e = g_edge[p];
            float w = __uint_as_float(e.y);
            float4 v = *((const float4*)(x + (size_t)e.x * DIM) + lane);
            acc.x += w * v.x; acc.y += w * v.y; acc.z += w * v.z; acc.w += w * v.w;
        }
        __stcs((float4*)(g_aggx + (size_t)n * NR + r * DIM) + lane, acc);
    }
}

// layer 2: g_agg2[n] = sum_{p in CSR[n]} g_h[src_p, :]  (same 4-way pipeline)
__global__ void k_agg2()
{
    int n = blockIdx.x * (blockDim.x >> 5) + (threadIdx.x >> 5);
    if (n >= N_NODES) return;
    int lane = threadIdx.x & 31;
    int beg = g_offn[n], end = g_offn[n + 1];
    float4 acc = make_float4(0.f, 0.f, 0.f, 0.f);
    int p = beg;
    for (; p + 4 <= end; p += 4) {
        uint2 e0 = g_edge[p];
        uint2 e1 = g_edge[p + 1];
        uint2 e2 = g_edge[p + 2];
        uint2 e3 = g_edge[p + 3];
        float4 v0 = *((const float4*)(g_h + (size_t)e0.x * DIM) + lane);
        float4 v1 = *((const float4*)(g_h + (size_t)e1.x * DIM) + lane);
        float4 v2 = *((const float4*)(g_h + (size_t)e2.x * DIM) + lane);
        float4 v3 = *((const float4*)(g_h + (size_t)e3.x * DIM) + lane);
        acc.x += v0.x; acc.y += v0.y; acc.z += v0.z; acc.w += v0.w;
        acc.x += v1.x; acc.y += v1.y; acc.z += v1.z; acc.w += v1.w;
        acc.x += v2.x; acc.y += v2.y; acc.z += v2.z; acc.w += v2.w;
        acc.x += v3.x; acc.y += v3.y; acc.z += v3.z; acc.w += v3.w;
    }
    for (; p < end; p++) {
        float4 v = *((const float4*)(g_h + (size_t)g_edge[p].x * DIM) + lane);
        acc.x += v.x; acc.y += v.y; acc.z += v.z; acc.w += v.w;
    }
    *((float4*)(g_agg2 + (size_t)n * DIM) + lane) = acc;
}

// ---------------- tf32 tensor-core GEMM (R8-proven, R15 cache hints) ----------------
// AMODE: 3=concat[g_agg2|g_h] (KT=256), 4=concat[g_aggx|Ap(x)] (KT=1152)
// BMODE: 2=concat[Bp|Bp2] (KT=256), 3=concat[g_W|Bp2(root)] (KT=1152)
// CMODE: 0=param, 2=g_h
// AMODE 4's aggx region is read-once -> __ldcs (evict-first).

__device__ __forceinline__ uint32_t f2tf(float f) {
    uint32_t u;
    asm volatile("cvt.rna.tf32.f32 %0, %1;" : "=r"(u) : "f"(f));
    return u;
}

__device__ __forceinline__ void mma_tf32(float* c, const uint32_t* a, const uint32_t* b) {
    asm volatile(
        "mma.sync.aligned.m16n8k8.row.col.f32.tf32.tf32.f32 "
        "{%0,%1,%2,%3}, {%4,%5,%6,%7}, {%8,%9}, {%0,%1,%2,%3};"
        : "+f"(c[0]), "+f"(c[1]), "+f"(c[2]), "+f"(c[3])
        : "r"(a[0]), "r"(a[1]), "r"(a[2]), "r"(a[3]), "r"(b[0]), "r"(b[1]));
}

template<int KT, int AMODE, int BMODE, int CMODE, bool ADD_C, bool HAS_BIAS>
__global__ __launch_bounds__(256, 2)
void k_gemm_tc(const float* __restrict__ Ap, const float* __restrict__ Bp,
               const float* __restrict__ Bp2, float* __restrict__ Cp,
               int M, int N, const float* __restrict__ bias)
{
    __shared__ __align__(16) uint32_t As[2][128][24];
    __shared__ __align__(16) uint32_t Bs[2][16][136];

    int tid  = threadIdx.x;
    int lane = tid & 31;
    int wid  = tid >> 5;
    int warp_m = wid & 1;
    int warp_n = wid >> 1;
    int m0 = blockIdx.y * 128;
    int n0 = blockIdx.x * 128;
    int r  = lane >> 2;
    int cq = lane & 3;

    float acc[4][4][4];
    #pragma unroll
    for (int mt = 0; mt < 4; mt++)
        #pragma unroll
        for (int nt = 0; nt < 4; nt++)
            #pragma unroll
            for (int i = 0; i < 4; i++) acc[mt][nt][i] = 0.f;

    float4 aReg[2], bReg[2];

    const int fa_m  = tid >> 2;
    const int fa_c4 = (tid & 3) * 4;
    const int fa_s0 = (fa_c4 & 8) | ((fa_c4 >> 2) & 1);

    auto LDG_chunk = [&](int k0) {       // k0 = element offset in K, multiple of 16
        const float* Asrc; int astride; int acol;
        bool streamA = false;
        if (AMODE == 3) {
            Asrc = (k0 < DIM) ? (const float*)g_agg2 : (const float*)g_h;
            acol = k0 & (DIM - 1); astride = DIM;
        } else if (AMODE == 4) {
            if (k0 < NR) { Asrc = (const float*)g_aggx; acol = k0; astride = NR; streamA = true; }
            else         { Asrc = Ap; acol = k0 - NR; astride = DIM; }
        } else { Asrc = Ap; acol = k0; astride = KT; }
        #pragma unroll
        for (int l = 0; l < 2; l++) {
            int gm = m0 + fa_m + l * 64;
            if (gm < M) {
                const float4* ap = (const float4*)&Asrc[(size_t)gm * astride + acol + fa_c4];
                aReg[l] = streamA ? __ldcs(ap) : *ap;
            } else {
                aReg[l] = make_float4(0.f, 0.f, 0.f, 0.f);
            }
        }
        const float* Bsrc; int brow;
        if (BMODE == 2)      { Bsrc = (k0 < DIM) ? Bp : Bp2; brow = k0 & (DIM - 1); }
        else if (BMODE == 3) { if (k0 < NR) { Bsrc = (const float*)g_W; brow = k0; }
                               else         { Bsrc = Bp2; brow = k0 - NR; } }
        else { Bsrc = Bp; brow = k0; }
        #pragma unroll
        for (int l = 0; l < 2; l++) {
            int idx = tid + l * 256;
            int kr = idx >> 5;
            int c = (idx & 31) * 4;
            bReg[l] = *(const float4*)&Bsrc[(size_t)(brow + kr) * N + n0 + c];
        }
    };

    auto STS_chunk = [&](auto bufc) {
        constexpr int buf = decltype(bufc)::value;
        #pragma unroll
        for (int l = 0; l < 2; l++) {
            int m = fa_m + l * 64;
            As[buf][m][fa_s0 + 0] = f2tf(aReg[l].x);
            As[buf][m][fa_s0 + 2] = f2tf(aReg[l].y);
            As[buf][m][fa_s0 + 4] = f2tf(aReg[l].z);
            As[buf][m][fa_s0 + 6] = f2tf(aReg[l].w);
        }
        #pragma unroll
        for (int l = 0; l < 2; l++) {
            int idx = tid + l * 256;
            int kr = idx >> 5;
            int c = (idx & 31) * 4;
            *(uint4*)&Bs[buf][kr][c] =
                make_uint4(f2tf(bReg[l].x), f2tf(bReg[l].y), f2tf(bReg[l].z), f2tf(bReg[l].w));
        }
    };

    auto MMA_chunk = [&](auto bufc) {
        constexpr int buf = decltype(bufc)::value;
        #pragma unroll
        for (int kk = 0; kk < 16; kk += 8) {
            uint32_t afr[4][4], bfr[4][2];
            #pragma unroll
            for (int mt = 0; mt < 4; mt++) {
                int mb = warp_m * 64 + mt * 16;
                uint2 lo = *(const uint2*)&As[buf][mb + r][kk + 2 * cq];
                uint2 hi = *(const uint2*)&As[buf][mb + r + 8][kk + 2 * cq];
                afr[mt][0] = lo.x; afr[mt][1] = hi.x;
                afr[mt][2] = lo.y; afr[mt][3] = hi.y;
            }
            #pragma unroll
            for (int nt = 0; nt < 4; nt++) {
                int nb = warp_n * 32 + nt * 8;
                bfr[nt][0] = Bs[buf][kk + cq][nb + r];
                bfr[nt][1] = Bs[buf][kk + cq + 4][nb + r];
            }
            #pragma unroll
            for (int mt = 0; mt < 4; mt++)
                #pragma unroll
                for (int nt = 0; nt < 4; nt++)
                    mma_tf32(acc[mt][nt], afr[mt], bfr[nt]);
        }
    };

    std::integral_constant<int, 0> B0;
    std::integral_constant<int, 1> B1;

    const int NC = KT / 16;
    LDG_chunk(0);
    STS_chunk(B0);
    __syncthreads();
    #pragma unroll 1
    for (int c = 0; c < NC; c += 2) {
        LDG_chunk((c + 1) * 16);
        MMA_chunk(B0);
        STS_chunk(B1);
        __syncthreads();
        if (c + 2 < NC) LDG_chunk((c + 2) * 16);
        MMA_chunk(B1);
        if (c + 2 < NC) {
            STS_chunk(B0);
            __syncthreads();
        }
    }

    float* C = (CMODE == 0) ? Cp : g_h;
    #pragma unroll
    for (int mt = 0; mt < 4; mt++) {
        int mA = m0 + warp_m * 64 + mt * 16 + r;
        #pragma unroll
        for (int nt = 0; nt < 4; nt++) {
            int n = n0 + warp_n * 32 + nt * 8 + 2 * cq;
            if (mA < M) {
                float2 v = make_float2(acc[mt][nt][0], acc[mt][nt][1]);
                if (HAS_BIAS) { v.x += bias[n]; v.y += bias[n + 1]; }
                if (ADD_C) {
                    float2 o = *(const float2*)&C[(size_t)mA * N + n];
                    v.x += o.x; v.y += o.y;
                }
                *(float2*)&C[(size_t)mA * N + n] = v;
            }
            int mB = mA + 8;
            if (mB < M) {
                float2 v = make_float2(acc[mt][nt][2], acc[mt][nt][3]);
                if (HAS_BIAS) { v.x += bias[n]; v.y += bias[n + 1]; }
                if (ADD_C) {
                    float2 o = *(const float2*)&C[(size_t)mB * N + n];
                    v.x += o.x; v.y += o.y;
                }
                *(float2*)&C[(size_t)mB * N + n] = v;
            }
        }
    }
}

// ---------------- launch ----------------
extern "C" void kernel_launch(void* const* d_in, const int* in_sizes, int n_in,
                              void* d_out, int out_size)
{
    const float* x      = (const float*)d_in[0];
    const int*   ei     = (const int*)d_in[1];    // int64 in reference -> delivered as int32
    const int*   et     = (const int*)d_in[2];
    const float* norm   = (const float*)d_in[3];
    const float* basis  = (const float*)d_in[4];
    const float* comp   = (const float*)d_in[5];
    const float* root   = (const float*)d_in[6];
    const float* bias1  = (const float*)d_in[7];
    const float* w_rel  = (const float*)d_in[8];
    const float* b_rel  = (const float*)d_in[9];
    const float* w_root = (const float*)d_in[10];
    float* out = (float*)d_out;

    const int MBLK = (N_NODES + 127) / 128;   // 391

    static cudaStream_t s_side = nullptr;
    static cudaEvent_t ev_fork = nullptr, ev_join = nullptr;
    if (s_side == nullptr) {
        cudaStreamCreateWithFlags(&s_side, cudaStreamNonBlocking);
        cudaEventCreateWithFlags(&ev_fork, cudaEventDisableTiming);
        cudaEventCreateWithFlags(&ev_join, cudaEventDisableTiming);
    }

    // ---- fork: weights on side stream, CSR build on main (critical path) ----
    cudaEventRecord(ev_fork, 0);
    cudaStreamWaitEvent(s_side, ev_fork, 0);
    k_W<<<(RELS * DIM * DIM + 255) / 256, 256, 0, s_side>>>(basis, comp);
    cudaEventRecord(ev_join, s_side);

    k_zero2<<<(N_NODES * RELS + 255) / 256, 256>>>();
    k_hist2<<<(N_EDGES + 255) / 256, 256>>>(ei, et);
    k_scan_p1<<<SCAN_G, SCAN_B>>>();
    k_scan_p3<<<SCAN_G, SCAN_B>>>();
    k_scatter2<<<(N_EDGES + 255) / 256, 256>>>(ei, et, norm);

    // per-relation aggregation of raw x (x is L2-resident)
    k_aggX<<<(N_NODES + 7) / 8, 256>>>(x);

    cudaStreamWaitEvent(0, ev_join, 0);
    // layer 1 in ONE concat GEMM: h = [aggX | x] @ [W2cat; root] + bias1, K=1152
    {
        dim3 grid(1, MBLK);
        k_gemm_tc<1152, 4, 3, 2, false, true><<<grid, 256>>>(x, nullptr, root, nullptr,
                                                             N_NODES, DIM, bias1);
    }
    // layer-2 aggregation -> g_agg2 (g_h is L2-resident)
    k_agg2<<<(N_NODES + 7) / 8, 256>>>();
    // out = [agg2, h] @ [w_rel; w_root] + b_rel   (fused K=256)
    {
        dim3 grid(1, MBLK);
        k_gemm_tc<256, 3, 2, 0, false, true><<<grid, 256>>>(nullptr, w_rel, w_root, out,
                                                            N_NODES, DIM, b_rel);
    }
}